// round 9
// baseline (speedup 1.0000x reference)
#include <cuda_runtime.h>
#include <cuda_bf16.h>
#include <math.h>
#include <stdint.h>

#define BB 2
#define SS 2048
#define HID 4096
#define NHQ 32
#define NHKV 8
#define HD 128
#define MR (BB*SS)          // 4096 rows
#define KVD (NHKV*HD)       // 1024
#define GRP (NHQ/NHKV)      // 4
#define GK 4096             // all GEMMs have K=4096

// ---------------- scratch (__device__ globals) ------------------------------
__device__ float g_Q[MR*HID];
__device__ float g_K[MR*KVD];
__device__ float g_cos[SS*(HD/2)];
__device__ float g_sin[SS*(HD/2)];
__device__ float g_sc[8];                  // 0:x 1:Wq 2:Wk 3:Wv 4:Wo 5:attnout
__device__ int8_t g_A0[MR*HID],  g_A1[MR*HID];       // activation limbs
__device__ int8_t g_Wq0[HID*HID], g_Wq1[HID*HID];    // W^T [N,K] limbs
__device__ int8_t g_Wk0[KVD*HID], g_Wk1[KVD*HID];
__device__ int8_t g_Wv0[KVD*HID], g_Wv1[KVD*HID];
__device__ int8_t g_Wo0[HID*HID], g_Wo1[HID*HID];
__device__ __nv_bfloat16 g_Qh[MR*HID], g_Ql[MR*HID];
__device__ __nv_bfloat16 g_Kh[MR*KVD], g_Kl[MR*KVD];
__device__ __nv_bfloat16 g_Vh[MR*KVD], g_Vl[MR*KVD];
__device__ __nv_bfloat16 g_Ath[MR*HID], g_Atl[MR*HID];

// ---------------- PTX helpers (portable sm_80-era ops) ----------------------
__device__ __forceinline__ uint32_t su32(const void* p) {
    uint32_t a;
    asm("{ .reg .u64 t; cvta.to.shared.u64 t, %1; cvt.u32.u64 %0, t; }"
        : "=r"(a) : "l"(p));
    return a;
}
__device__ __forceinline__ void cp16(uint32_t sa, const void* g) {
    asm volatile("cp.async.cg.shared.global [%0], [%1], 16;\n" :: "r"(sa), "l"(g));
}
#define CP_COMMIT() asm volatile("cp.async.commit_group;\n")
#define LDSM_X4(r, a) \
    asm volatile("ldmatrix.sync.aligned.m8n8.x4.shared.b16 {%0,%1,%2,%3}, [%4];" \
        : "=r"((r)[0]), "=r"((r)[1]), "=r"((r)[2]), "=r"((r)[3]) : "r"(a))
#define LDSM_X4T(r, a) \
    asm volatile("ldmatrix.sync.aligned.m8n8.x4.trans.shared.b16 {%0,%1,%2,%3}, [%4];" \
        : "=r"((r)[0]), "=r"((r)[1]), "=r"((r)[2]), "=r"((r)[3]) : "r"(a))
#define MMA4(d, a, b0, b1) \
    asm volatile("mma.sync.aligned.m16n8k16.row.col.f32.bf16.bf16.f32 " \
        "{%0,%1,%2,%3},{%4,%5,%6,%7},{%8,%9},{%0,%1,%2,%3};" \
        : "+f"((d)[0]), "+f"((d)[1]), "+f"((d)[2]), "+f"((d)[3]) \
        : "r"((a)[0]), "r"((a)[1]), "r"((a)[2]), "r"((a)[3]), "r"(b0), "r"(b1))
#define MMAI8(d, a, b0_, b1_) \
    asm volatile("mma.sync.aligned.m16n8k32.row.col.s32.s8.s8.s32 " \
        "{%0,%1,%2,%3},{%4,%5,%6,%7},{%8,%9},{%0,%1,%2,%3};" \
        : "+r"((d)[0]), "+r"((d)[1]), "+r"((d)[2]), "+r"((d)[3]) \
        : "r"((a)[0]), "r"((a)[1]), "r"((a)[2]), "r"((a)[3]), "r"(b0_), "r"(b1_))

__device__ __forceinline__ uint32_t swz256(uint32_t o) {   // 256B rows
    return o ^ (((o >> 8) & 7u) << 4);
}
__device__ __forceinline__ uint32_t swz128(uint32_t o) {   // 128B rows
    return o ^ (((o >> 7) & 7u) << 4);
}
__device__ __forceinline__ void pk2(float x, float y, uint32_t& hi, uint32_t& lo) {
    __nv_bfloat16 hx = __float2bfloat16(x), hy = __float2bfloat16(y);
    hi = ((uint32_t)*(uint16_t*)&hy << 16) | *(uint16_t*)&hx;
    __nv_bfloat16 lx = __float2bfloat16(x - __bfloat162float(hx));
    __nv_bfloat16 ly = __float2bfloat16(y - __bfloat162float(hy));
    lo = ((uint32_t)*(uint16_t*)&ly << 16) | *(uint16_t*)&lx;
}

// ---------------------------------------------------------------------------
// 2-limb int8 tensor-core GEMM (EXACT product): C = A @ Bt^T
// x = sc/127*(a0 + a1/254), all three limb products accumulated in s32.
// CTA 128x64, BK=64, double-buffered cp.async. 8 warps = 2m x 4n of 64x16.
// smem rows 128B = [limb0 64B | limb1 64B].
// ---------------------------------------------------------------------------
#define GI_SMEM 49152

__global__ void __launch_bounds__(256) gemm_i8(
    const int8_t* __restrict__ A0, const int8_t* __restrict__ A1,
    const int8_t* __restrict__ B0, const int8_t* __restrict__ B1,
    float* __restrict__ Cf,
    __nv_bfloat16* __restrict__ Oh, __nv_bfloat16* __restrict__ Ol,
    int N, const float* __restrict__ scA, const float* __restrict__ scB)
{
    extern __shared__ __align__(1024) char smg[];
    const uint32_t sb = su32(smg);
    const int tid = threadIdx.x, w = tid >> 5, l = tid & 31;
    const int n0 = blockIdx.x * 64, m0 = blockIdx.y * 128;
    const int wm = (w & 1) * 64, wn = (w >> 1) * 16;

    auto loadChunk = [&](int c) {
        const uint32_t st = sb + (uint32_t)(c & 1) * 24576;
        const int k0 = c * 64;
        #pragma unroll
        for (int t = 0; t < 4; t++) {                 // A: 128 rows x 128B
            int j = tid + t * 256;
            int r = j >> 3, c8 = j & 7;
            uint32_t o = swz128((uint32_t)(r * 128 + c8 * 16));
            const int8_t* ga = (c8 < 4 ? A0 : A1) +
                (size_t)(m0 + r) * GK + k0 + (c8 & 3) * 16;
            cp16(st + o, ga);
        }
        #pragma unroll
        for (int t = 0; t < 2; t++) {                 // B: 64 rows x 128B
            int j = tid + t * 256;
            int r = j >> 3, c8 = j & 7;
            uint32_t o = swz128((uint32_t)(r * 128 + c8 * 16));
            const int8_t* gb = (c8 < 4 ? B0 : B1) +
                (size_t)(n0 + r) * GK + k0 + (c8 & 3) * 16;
            cp16(st + 16384 + o, gb);
        }
        CP_COMMIT();
    };

    int32_t acc0[4][2][4], acc1[4][2][4], acc2[4][2][4];
    #pragma unroll
    for (int mf = 0; mf < 4; mf++)
        #pragma unroll
        for (int nb = 0; nb < 2; nb++)
            #pragma unroll
            for (int q = 0; q < 4; q++)
                { acc0[mf][nb][q] = 0; acc1[mf][nb][q] = 0; acc2[mf][nb][q] = 0; }

    loadChunk(0);

    const int NC = GK / 64;
    for (int c = 0; c < NC; c++) {
        if (c + 1 < NC) {
            loadChunk(c + 1);
            asm volatile("cp.async.wait_group 1;\n");
        } else {
            asm volatile("cp.async.wait_group 0;\n");
        }
        __syncthreads();
        const uint32_t st = sb + (uint32_t)(c & 1) * 24576;

        #pragma unroll
        for (int ks = 0; ks < 2; ks++) {
            uint32_t af0[4][4], af1[4][4];
            #pragma unroll
            for (int mf = 0; mf < 4; mf++) {
                uint32_t base = (uint32_t)((wm + mf * 16 + (l & 15)) * 128 +
                                           ks * 32 + ((l & 16) ? 16 : 0));
                LDSM_X4(af0[mf], st + swz128(base));
                LDSM_X4(af1[mf], st + swz128(base + 64));
            }
            uint32_t bf0[4], bf1[4];
            {
                uint32_t base = (uint32_t)((wn + (l & 7) + ((l & 16) ? 8 : 0)) * 128 +
                                           ks * 32 + ((l & 8) ? 16 : 0));
                LDSM_X4(bf0, st + 16384 + swz128(base));
                LDSM_X4(bf1, st + 16384 + swz128(base + 64));
            }
            #pragma unroll
            for (int mf = 0; mf < 4; mf++) {
                MMAI8(acc0[mf][0], af0[mf], bf0[0], bf0[1]);
                MMAI8(acc0[mf][1], af0[mf], bf0[2], bf0[3]);
                MMAI8(acc1[mf][0], af0[mf], bf1[0], bf1[1]);
                MMAI8(acc1[mf][1], af0[mf], bf1[2], bf1[3]);
                MMAI8(acc1[mf][0], af1[mf], bf0[0], bf0[1]);
                MMAI8(acc1[mf][1], af1[mf], bf0[2], bf0[3]);
                MMAI8(acc2[mf][0], af1[mf], bf1[0], bf1[1]);
                MMAI8(acc2[mf][1], af1[mf], bf1[2], bf1[3]);
            }
        }
        __syncthreads();
    }

    const float sAB = scA[0] * scB[0] * (1.0f / (127.0f * 127.0f));
    const float w1 = 1.0f / 254.0f, w2 = 1.0f / 64516.0f;
    #pragma unroll
    for (int mf = 0; mf < 4; mf++) {
        int r0 = m0 + wm + mf * 16 + (l >> 2);
        #pragma unroll
        for (int nb = 0; nb < 2; nb++) {
            int cc = n0 + wn + nb * 8 + (l & 3) * 2;
            float y0 = sAB * ((float)acc0[mf][nb][0] + (float)acc1[mf][nb][0] * w1
                              + (float)acc2[mf][nb][0] * w2);
            float y1 = sAB * ((float)acc0[mf][nb][1] + (float)acc1[mf][nb][1] * w1
                              + (float)acc2[mf][nb][1] * w2);
            float y2 = sAB * ((float)acc0[mf][nb][2] + (float)acc1[mf][nb][2] * w1
                              + (float)acc2[mf][nb][2] * w2);
            float y3 = sAB * ((float)acc0[mf][nb][3] + (float)acc1[mf][nb][3] * w1
                              + (float)acc2[mf][nb][3] * w2);
            if (Cf) {
                *(float2*)(Cf + (size_t)r0 * N + cc)       = make_float2(y0, y1);
                *(float2*)(Cf + (size_t)(r0 + 8) * N + cc) = make_float2(y2, y3);
            } else {
                uint32_t hi, lo;
                pk2(y0, y1, hi, lo);
                *(uint32_t*)(Oh + (size_t)r0 * N + cc) = hi;
                *(uint32_t*)(Ol + (size_t)r0 * N + cc) = lo;
                pk2(y2, y3, hi, lo);
                *(uint32_t*)(Oh + (size_t)(r0 + 8) * N + cc) = hi;
                *(uint32_t*)(Ol + (size_t)(r0 + 8) * N + cc) = lo;
            }
        }
    }
}

// ---------------------------------------------------------------------------
// scale computation + quantization (limb1 scale = 254)
// ---------------------------------------------------------------------------
__global__ void reset_sc() { if (threadIdx.x < 8) g_sc[threadIdx.x] = 0.f; }

__global__ void maxabs_k(const float* __restrict__ X, int n4, int idx)
{
    int i = blockIdx.x * 256 + threadIdx.x;
    float m = 0.f;
    if (i < n4) {
        float4 v = *(const float4*)(X + (size_t)i * 4);
        m = fmaxf(fmaxf(fabsf(v.x), fabsf(v.y)), fmaxf(fabsf(v.z), fabsf(v.w)));
    }
    #pragma unroll
    for (int o = 16; o; o >>= 1) m = fmaxf(m, __shfl_xor_sync(0xffffffffu, m, o));
    if ((threadIdx.x & 31) == 0 && m > 0.f)
        atomicMax((int*)&g_sc[idx], __float_as_int(m));
}

__global__ void maxabs2_k(const __nv_bfloat16* __restrict__ H,
                          const __nv_bfloat16* __restrict__ L, int n4, int idx)
{
    int i = blockIdx.x * 256 + threadIdx.x;
    float m = 0.f;
    if (i < n4) {
        __nv_bfloat162 h0 = *(const __nv_bfloat162*)(H + (size_t)i * 4);
        __nv_bfloat162 h1 = *(const __nv_bfloat162*)(H + (size_t)i * 4 + 2);
        __nv_bfloat162 l0 = *(const __nv_bfloat162*)(L + (size_t)i * 4);
        __nv_bfloat162 l1 = *(const __nv_bfloat162*)(L + (size_t)i * 4 + 2);
        m = fmaxf(fmaxf(fabsf(__bfloat162float(h0.x) + __bfloat162float(l0.x)),
                        fabsf(__bfloat162float(h0.y) + __bfloat162float(l0.y))),
                  fmaxf(fabsf(__bfloat162float(h1.x) + __bfloat162float(l1.x)),
                        fabsf(__bfloat162float(h1.y) + __bfloat162float(l1.y))));
    }
    #pragma unroll
    for (int o = 16; o; o >>= 1) m = fmaxf(m, __shfl_xor_sync(0xffffffffu, m, o));
    if ((threadIdx.x & 31) == 0 && m > 0.f)
        atomicMax((int*)&g_sc[idx], __float_as_int(m));
}

__device__ __forceinline__ void q2(float v, float inv, int8_t& a0, int8_t& a1) {
    float t = v * inv;
    float r0 = rintf(t);
    a0 = (int8_t)(int)r0;
    a1 = (int8_t)(int)rintf((t - r0) * 254.0f);
}

__global__ void quantA_k(const float* __restrict__ X,
                         int8_t* __restrict__ A0, int8_t* __restrict__ A1,
                         int n4, int idx)
{
    int i = blockIdx.x * 256 + threadIdx.x;
    if (i >= n4) return;
    float inv = 127.0f / g_sc[idx];
    float4 v = *(const float4*)(X + (size_t)i * 4);
    int8_t a[4], b[4];
    q2(v.x, inv, a[0], b[0]); q2(v.y, inv, a[1], b[1]);
    q2(v.z, inv, a[2], b[2]); q2(v.w, inv, a[3], b[3]);
    *(uint32_t*)(A0 + (size_t)i * 4) = *(uint32_t*)a;
    *(uint32_t*)(A1 + (size_t)i * 4) = *(uint32_t*)b;
}

__global__ void quant2_k(const __nv_bfloat16* __restrict__ H,
                         const __nv_bfloat16* __restrict__ L,
                         int8_t* __restrict__ A0, int8_t* __restrict__ A1,
                         int n4, int idx)
{
    int i = blockIdx.x * 256 + threadIdx.x;
    if (i >= n4) return;
    float inv = 127.0f / g_sc[idx];
    __nv_bfloat162 h0 = *(const __nv_bfloat162*)(H + (size_t)i * 4);
    __nv_bfloat162 h1 = *(const __nv_bfloat162*)(H + (size_t)i * 4 + 2);
    __nv_bfloat162 l0 = *(const __nv_bfloat162*)(L + (size_t)i * 4);
    __nv_bfloat162 l1 = *(const __nv_bfloat162*)(L + (size_t)i * 4 + 2);
    float v0 = __bfloat162float(h0.x) + __bfloat162float(l0.x);
    float v1 = __bfloat162float(h0.y) + __bfloat162float(l0.y);
    float v2 = __bfloat162float(h1.x) + __bfloat162float(l1.x);
    float v3 = __bfloat162float(h1.y) + __bfloat162float(l1.y);
    int8_t a[4], b[4];
    q2(v0, inv, a[0], b[0]); q2(v1, inv, a[1], b[1]);
    q2(v2, inv, a[2], b[2]); q2(v3, inv, a[3], b[3]);
    *(uint32_t*)(A0 + (size_t)i * 4) = *(uint32_t*)a;
    *(uint32_t*)(A1 + (size_t)i * 4) = *(uint32_t*)b;
}

__global__ void quantT_k(const float* __restrict__ W,
                         int8_t* __restrict__ B0, int8_t* __restrict__ B1,
                         int K, int N, int idx)
{
    __shared__ float t[32][33];
    const int n0 = blockIdx.x * 32, k0 = blockIdx.y * 32;
    const int tx = threadIdx.x, ty = threadIdx.y;
    #pragma unroll
    for (int r = ty; r < 32; r += 8)
        t[r][tx] = W[(size_t)(k0 + r) * N + n0 + tx];
    __syncthreads();
    float inv = 127.0f / g_sc[idx];
    #pragma unroll
    for (int r = ty; r < 32; r += 8) {
        float v = t[tx][r];
        int8_t b0, b1;
        q2(v, inv, b0, b1);
        size_t o = (size_t)(n0 + r) * K + k0 + tx;
        B0[o] = b0;
        B1[o] = b1;
    }
}

// ---------------------------------------------------------------------------
// RoPE (reference-exact f32 rounding of angles)
// ---------------------------------------------------------------------------
__global__ void rope_table_k()
{
    int idx = blockIdx.x * blockDim.x + threadIdx.x;
    if (idx >= SS * 64) return;
    int pos = idx >> 6;
    int i   = idx & 63;
    float invf = (float)pow(10000.0, -((double)i) / 64.0);
    float angf = (float)pos * invf;
    double ang = (double)angf;
    g_cos[idx] = (float)cos(ang);
    g_sin[idx] = (float)sin(ang);
}

__global__ void rope_split_k(const float* __restrict__ X,
                             __nv_bfloat16* __restrict__ H,
                             __nv_bfloat16* __restrict__ L,
                             int nh, float scale)
{
    int idx = blockIdx.x * blockDim.x + threadIdx.x;
    int total = MR * nh * 64;
    if (idx >= total) return;
    int half = idx & 63;
    int h    = (idx >> 6) % nh;
    int r    = idx / (64 * nh);
    int s    = r % SS;
    size_t base = (size_t)r * nh * HD + (size_t)h * HD;
    float c  = g_cos[s * 64 + half];
    float sn = g_sin[s * 64 + half];
    float x1 = X[base + half];
    float x2 = X[base + half + 64];
    float y1 = (x1 * c - x2 * sn) * scale;
    float y2 = (x2 * c + x1 * sn) * scale;
    __nv_bfloat16 h1 = __float2bfloat16(y1);
    __nv_bfloat16 h2 = __float2bfloat16(y2);
    H[base + half]      = h1;
    H[base + half + 64] = h2;
    L[base + half]      = __float2bfloat16(y1 - __bfloat162float(h1));
    L[base + half + 64] = __float2bfloat16(y2 - __bfloat162float(h2));
}

// ---------------------------------------------------------------------------
// FlashAttention-2 mma.sync bf16 split (proven R7 kernel, unchanged).
// ---------------------------------------------------------------------------
#define ATT_SMEM 196608

__global__ void __launch_bounds__(256) attn_mma()
{
    extern __shared__ __align__(1024) char smdyn[];
    const int qb = blockIdx.x, h = blockIdx.y, b = blockIdx.z;
    const int kvh = h / GRP;
    const int tid = threadIdx.x, w = tid >> 5, l = tid & 31;
    const uint32_t sb = su32(smdyn);
    const uint32_t Qh_s = sb;
    const uint32_t KV0  = sb + 65536;

    {
        const __nv_bfloat16* qh = g_Qh + (size_t)(b * SS + qb * 128) * HID + h * HD;
        const __nv_bfloat16* ql = g_Ql + (size_t)(b * SS + qb * 128) * HID + h * HD;
        #pragma unroll
        for (int t = 0; t < 8; t++) {
            int j = tid + t * 256;
            int r = j >> 4, c = j & 15;
            uint32_t o = swz256((uint32_t)(r * 256 + c * 16));
            cp16(Qh_s + o,         (const void*)(qh + (size_t)r * HID + c * 8));
            cp16(Qh_s + 32768 + o, (const void*)(ql + (size_t)r * HID + c * 8));
        }
        CP_COMMIT();
    }

    const int NT = 2 * qb + 2;
    auto loadKV = [&](int kt) {
        const uint32_t st = KV0 + (uint32_t)(kt & 1) * 65536;
        const size_t rb = (size_t)(b * SS + kt * 64) * KVD + kvh * HD;
        #pragma unroll
        for (int t = 0; t < 4; t++) {
            int j = tid + t * 256;
            int r = j >> 4, c = j & 15;
            uint32_t o = swz256((uint32_t)(r * 256 + c * 16));
            size_t g = rb + (size_t)r * KVD + c * 8;
            cp16(st +         o, (const void*)(g_Kh + g));
            cp16(st + 16384 + o, (const void*)(g_Kl + g));
            cp16(st + 32768 + o, (const void*)(g_Vh + g));
            cp16(st + 49152 + o, (const void*)(g_Vl + g));
        }
        CP_COMMIT();
    };
    loadKV(0);

    const int m0 = w * 16;
    const int qg0 = qb * 128 + m0 + (l >> 2);
    float O[16][4];
    #pragma unroll
    for (int f = 0; f < 16; f++)
        { O[f][0] = 0.f; O[f][1] = 0.f; O[f][2] = 0.f; O[f][3] = 0.f; }
    float mr0 = -1e30f, mr1 = -1e30f, sl0 = 0.f, sl1 = 0.f;

    for (int kt = 0; kt < NT; kt++) {
        if (kt + 1 < NT) {
            loadKV(kt + 1);
            asm volatile("cp.async.wait_group 1;\n");
        } else {
            asm volatile("cp.async.wait_group 0;\n");
        }
        __syncthreads();

        const uint32_t st = KV0 + (uint32_t)(kt & 1) * 65536;

        float s[8][4];
        #pragma unroll
        for (int nb = 0; nb < 8; nb++)
            { s[nb][0] = 0.f; s[nb][1] = 0.f; s[nb][2] = 0.f; s[nb][3] = 0.f; }

        #pragma unroll
        for (int ks = 0; ks < 8; ks++) {
            uint32_t aQh[4], aQl[4];
            uint32_t aaddr = Qh_s + swz256(
                (uint32_t)((m0 + (l & 15)) * 256 + ks * 32 + ((l & 16) ? 16 : 0)));
            LDSM_X4(aQh, aaddr);
            LDSM_X4(aQl, aaddr + 32768);
            #pragma unroll
            for (int nb2 = 0; nb2 < 4; nb2++) {
                uint32_t brow = (uint32_t)(nb2 * 16 + (l & 7) + ((l & 16) ? 8 : 0));
                uint32_t baddr = st + swz256(brow * 256 + ks * 32 + ((l & 8) ? 16 : 0));
                uint32_t bh[4], bl[4];
                LDSM_X4(bh, baddr);
                LDSM_X4(bl, baddr + 16384);
                MMA4(s[2*nb2],   aQh, bh[0], bh[1]);
                MMA4(s[2*nb2+1], aQh, bh[2], bh[3]);
                MMA4(s[2*nb2],   aQh, bl[0], bl[1]);
                MMA4(s[2*nb2+1], aQh, bl[2], bl[3]);
                MMA4(s[2*nb2],   aQl, bh[0], bh[1]);
                MMA4(s[2*nb2+1], aQl, bh[2], bh[3]);
            }
        }

        const int kgb = kt * 64 + (l & 3) * 2;
        float mx0 = -1e30f, mx1 = -1e30f;
        #pragma unroll
        for (int nb = 0; nb < 8; nb++) {
            int kg = kgb + nb * 8;
            if (kg     > qg0)     s[nb][0] = -1e30f;
            if (kg + 1 > qg0)     s[nb][1] = -1e30f;
            if (kg     > qg0 + 8) s[nb][2] = -1e30f;
            if (kg + 1 > qg0 + 8) s[nb][3] = -1e30f;
            mx0 = fmaxf(mx0, fmaxf(s[nb][0], s[nb][1]));
            mx1 = fmaxf(mx1, fmaxf(s[nb][2], s[nb][3]));
        }
        mx0 = fmaxf(mx0, __shfl_xor_sync(0xffffffffu, mx0, 1));
        mx0 = fmaxf(mx0, __shfl_xor_sync(0xffffffffu, mx0, 2));
        mx1 = fmaxf(mx1, __shfl_xor_sync(0xffffffffu, mx1, 1));
        mx1 = fmaxf(mx1, __shfl_xor_sync(0xffffffffu, mx1, 2));

        float mn0 = fmaxf(mr0, mx0), mn1 = fmaxf(mr1, mx1);
        float al0 = __expf(mr0 - mn0), al1 = __expf(mr1 - mn1);
        mr0 = mn0; mr1 = mn1;
        float sum0 = 0.f, sum1 = 0.f;
        #pragma unroll
        for (int nb = 0; nb < 8; nb++) {
            s[nb][0] = __expf(s[nb][0] - mn0);
            s[nb][1] = __expf(s[nb][1] - mn0);
            s[nb][2] = __expf(s[nb][2] - mn1);
            s[nb][3] = __expf(s[nb][3] - mn1);
            sum0 += s[nb][0] + s[nb][1];
            sum1 += s[nb][2] + s[nb][3];
        }
        sum0 += __shfl_xor_sync(0xffffffffu, sum0, 1);
        sum0 += __shfl_xor_sync(0xffffffffu, sum0, 2);
        sum1 += __shfl_xor_sync(0xffffffffu, sum1, 1);
        sum1 += __shfl_xor_sync(0xffffffffu, sum1, 2);
        sl0 = sl0 * al0 + sum0;
        sl1 = sl1 * al1 + sum1;
        #pragma unroll
        for (int f = 0; f < 16; f++) {
            O[f][0] *= al0; O[f][1] *= al0; O[f][2] *= al1; O[f][3] *= al1;
        }

        #pragma unroll
        for (int j = 0; j < 4; j++) {
            uint32_t ph[4], pl[4];
            pk2(s[2*j][0],   s[2*j][1],   ph[0], pl[0]);
            pk2(s[2*j][2],   s[2*j][3],   ph[1], pl[1]);
            pk2(s[2*j+1][0], s[2*j+1][1], ph[2], pl[2]);
            pk2(s[2*j+1][2], s[2*j+1][3], ph[3], pl[3]);
            uint32_t vrow = (uint32_t)(j * 16 + (l & 7) + ((l & 8) ? 8 : 0));
            #pragma unroll
            for (int nb2 = 0; nb2 < 8; nb2++) {
                uint32_t vaddr = st + 32768 +
                    swz256(vrow * 256 + nb2 * 32 + ((l & 16) ? 16 : 0));
                uint32_t vh[4], vl[4];
                LDSM_X4T(vh, vaddr);
                LDSM_X4T(vl, vaddr + 16384);
                MMA4(O[2*nb2],   ph, vh[0], vh[1]);
                MMA4(O[2*nb2+1], ph, vh[2], vh[3]);
                MMA4(O[2*nb2],   ph, vl[0], vl[1]);
                MMA4(O[2*nb2+1], ph, vl[2], vl[3]);
                MMA4(O[2*nb2],   pl, vh[0], vh[1]);
                MMA4(O[2*nb2+1], pl, vh[2], vh[3]);
            }
        }
        __syncthreads();
    }

    const float i0 = 1.0f / sl0, i1 = 1.0f / sl1;
    size_t base0 = (size_t)(b * SS + qg0) * HID + (size_t)h * HD;
    size_t base1 = base0 + (size_t)8 * HID;
    #pragma unroll
    for (int nb = 0; nb < 16; nb++) {
        int col = nb * 8 + (l & 3) * 2;
        uint32_t hi, lo;
        pk2(O[nb][0] * i0, O[nb][1] * i0, hi, lo);
        *(uint32_t*)(g_Ath + base0 + col) = hi;
        *(uint32_t*)(g_Atl + base0 + col) = lo;
        pk2(O[nb][2] * i1, O[nb][3] * i1, hi, lo);
        *(uint32_t*)(g_Ath + base1 + col) = hi;
        *(uint32_t*)(g_Atl + base1 + col) = lo;
    }
}

// ---------------------------------------------------------------------------
extern "C" void kernel_launch(void* const* d_in, const int* in_sizes, int n_in,
                              void* d_out, int out_size)
{
    (void)in_sizes; (void)n_in; (void)out_size;
    const float* x  = (const float*)d_in[0];
    const float* Wq = (const float*)d_in[1];
    const float* Wk = (const float*)d_in[2];
    const float* Wv = (const float*)d_in[3];
    const float* Wo = (const float*)d_in[4];
    float* out = (float*)d_out;

    float *Qp, *Kp, *scp;
    int8_t *a0, *a1, *wq0, *wq1, *wk0, *wk1, *wv0, *wv1, *wo0, *wo1;
    __nv_bfloat16 *qh, *ql, *kh, *kl, *vh, *vl, *ath, *atl;
    cudaGetSymbolAddress((void**)&Qp, g_Q);
    cudaGetSymbolAddress((void**)&Kp, g_K);
    cudaGetSymbolAddress((void**)&scp, g_sc);
    cudaGetSymbolAddress((void**)&a0, g_A0);   cudaGetSymbolAddress((void**)&a1, g_A1);
    cudaGetSymbolAddress((void**)&wq0, g_Wq0); cudaGetSymbolAddress((void**)&wq1, g_Wq1);
    cudaGetSymbolAddress((void**)&wk0, g_Wk0); cudaGetSymbolAddress((void**)&wk1, g_Wk1);
    cudaGetSymbolAddress((void**)&wv0, g_Wv0); cudaGetSymbolAddress((void**)&wv1, g_Wv1);
    cudaGetSymbolAddress((void**)&wo0, g_Wo0); cudaGetSymbolAddress((void**)&wo1, g_Wo1);
    cudaGetSymbolAddress((void**)&qh, g_Qh);   cudaGetSymbolAddress((void**)&ql, g_Ql);
    cudaGetSymbolAddress((void**)&kh, g_Kh);   cudaGetSymbolAddress((void**)&kl, g_Kl);
    cudaGetSymbolAddress((void**)&vh, g_Vh);   cudaGetSymbolAddress((void**)&vl, g_Vl);
    cudaGetSymbolAddress((void**)&ath, g_Ath); cudaGetSymbolAddress((void**)&atl, g_Atl);

    cudaFuncSetAttribute(gemm_i8, cudaFuncAttributeMaxDynamicSharedMemorySize, GI_SMEM);
    cudaFuncSetAttribute(attn_mma, cudaFuncAttributeMaxDynamicSharedMemorySize, ATT_SMEM);

    // scales (reset every call -> deterministic under graph replay)
    reset_sc<<<1, 32>>>();
    maxabs_k<<<(MR*HID/4 + 255)/256, 256>>>(x,  MR*HID/4, 0);
    maxabs_k<<<(HID*HID/4 + 255)/256, 256>>>(Wq, HID*HID/4, 1);
    maxabs_k<<<(HID*KVD/4 + 255)/256, 256>>>(Wk, HID*KVD/4, 2);
    maxabs_k<<<(HID*KVD/4 + 255)/256, 256>>>(Wv, HID*KVD/4, 3);
    maxabs_k<<<(HID*HID/4 + 255)/256, 256>>>(Wo, HID*HID/4, 4);

    // quantization
    quantA_k<<<(MR*HID/4 + 255)/256, 256>>>(x, a0, a1, MR*HID/4, 0);
    quantT_k<<<dim3(HID/32, HID/32), dim3(32, 8)>>>(Wq, wq0, wq1, HID, HID, 1);
    quantT_k<<<dim3(KVD/32, HID/32), dim3(32, 8)>>>(Wk, wk0, wk1, HID, KVD, 2);
    quantT_k<<<dim3(KVD/32, HID/32), dim3(32, 8)>>>(Wv, wv0, wv1, HID, KVD, 3);
    quantT_k<<<dim3(HID/32, HID/32), dim3(32, 8)>>>(Wo, wo0, wo1, HID, HID, 4);

    rope_table_k<<<(SS * 64 + 255) / 256, 256>>>();

    // projections (int8 tensor cores, exact 2-limb product)
    gemm_i8<<<dim3(HID/64, MR/128), 256, GI_SMEM>>>(
        a0, a1, wq0, wq1, Qp, nullptr, nullptr, HID, scp + 0, scp + 1);
    gemm_i8<<<dim3(KVD/64, MR/128), 256, GI_SMEM>>>(
        a0, a1, wk0, wk1, Kp, nullptr, nullptr, KVD, scp + 0, scp + 2);
    gemm_i8<<<dim3(KVD/64, MR/128), 256, GI_SMEM>>>(
        a0, a1, wv0, wv1, nullptr, vh, vl, KVD, scp + 0, scp + 3);

    const float scale = 0.08838834764831845f;   // 1/sqrt(128)
    rope_split_k<<<(MR * NHQ  * 64 + 255) / 256, 256>>>(Qp, qh, ql, NHQ, scale);
    rope_split_k<<<(MR * NHKV * 64 + 255) / 256, 256>>>(Kp, kh, kl, NHKV, 1.0f);

    attn_mma<<<dim3(SS / 128, NHQ, BB), 256, ATT_SMEM>>>();

    // output projection
    maxabs2_k<<<(MR*HID/4 + 255)/256, 256>>>(ath, atl, MR*HID/4, 5);
    quant2_k<<<(MR*HID/4 + 255)/256, 256>>>(ath, atl, a0, a1, MR*HID/4, 5);
    gemm_i8<<<dim3(HID/64, MR/128), 256, GI_SMEM>>>(
        a0, a1, wo0, wo1, out, nullptr, nullptr, HID, scp + 5, scp + 4);
}

// round 12
// speedup vs baseline: 3.3831x; 3.3831x over previous
#include <cuda_runtime.h>
#include <cuda_bf16.h>
#include <math.h>
#include <stdint.h>

#define BB 2
#define SS 2048
#define HID 4096
#define NHQ 32
#define NHKV 8
#define HD 128
#define MR (BB*SS)          // 4096 rows
#define KVD (NHKV*HD)       // 1024
#define GRP (NHQ/NHKV)      // 4
#define GK 4096             // all GEMMs have K=4096

// ---------------- scratch (__device__ globals) ------------------------------
__device__ float g_Q[MR*HID];
__device__ float g_K[MR*KVD];
__device__ float g_cos[SS*(HD/2)];
__device__ float g_sin[SS*(HD/2)];
__device__ __nv_bfloat16 g_xh[MR*HID],  g_xl[MR*HID];
__device__ __nv_bfloat16 g_Wqh[HID*HID], g_Wql[HID*HID];   // [K,N] row-major
__device__ __nv_bfloat16 g_Wkh[HID*KVD], g_Wkl[HID*KVD];
__device__ __nv_bfloat16 g_Wvh[HID*KVD], g_Wvl[HID*KVD];
__device__ __nv_bfloat16 g_Woh[HID*HID], g_Wol[HID*HID];
__device__ __nv_bfloat16 g_Qh[MR*HID], g_Ql[MR*HID];
__device__ __nv_bfloat16 g_Kh[MR*KVD], g_Kl[MR*KVD];
__device__ __nv_bfloat16 g_Vh[MR*KVD], g_Vl[MR*KVD];
__device__ __nv_bfloat16 g_Ath[MR*HID], g_Atl[MR*HID];

// ---------------- PTX helpers (portable sm_80-era ops) ----------------------
__device__ __forceinline__ uint32_t su32(const void* p) {
    uint32_t a;
    asm("{ .reg .u64 t; cvta.to.shared.u64 t, %1; cvt.u32.u64 %0, t; }"
        : "=r"(a) : "l"(p));
    return a;
}
__device__ __forceinline__ void cp16(uint32_t sa, const void* g) {
    asm volatile("cp.async.cg.shared.global [%0], [%1], 16;\n" :: "r"(sa), "l"(g));
}
#define CP_COMMIT() asm volatile("cp.async.commit_group;\n")
#define LDSM_X4(r, a) \
    asm volatile("ldmatrix.sync.aligned.m8n8.x4.shared.b16 {%0,%1,%2,%3}, [%4];" \
        : "=r"((r)[0]), "=r"((r)[1]), "=r"((r)[2]), "=r"((r)[3]) : "r"(a))
#define LDSM_X4T(r, a) \
    asm volatile("ldmatrix.sync.aligned.m8n8.x4.trans.shared.b16 {%0,%1,%2,%3}, [%4];" \
        : "=r"((r)[0]), "=r"((r)[1]), "=r"((r)[2]), "=r"((r)[3]) : "r"(a))
#define MMA4(d, a, b0, b1) \
    asm volatile("mma.sync.aligned.m16n8k16.row.col.f32.bf16.bf16.f32 " \
        "{%0,%1,%2,%3},{%4,%5,%6,%7},{%8,%9},{%0,%1,%2,%3};" \
        : "+f"((d)[0]), "+f"((d)[1]), "+f"((d)[2]), "+f"((d)[3]) \
        : "r"((a)[0]), "r"((a)[1]), "r"((a)[2]), "r"((a)[3]), "r"(b0), "r"(b1))

__device__ __forceinline__ uint32_t swz256(uint32_t o) {   // 256B rows
    return o ^ (((o >> 8) & 7u) << 4);
}
__device__ __forceinline__ uint32_t swz128(uint32_t o) {   // 128B rows
    return o ^ (((o >> 7) & 7u) << 4);
}
__device__ __forceinline__ uint32_t swz512(uint32_t o) {   // 512B rows
    return o ^ (((o >> 9) & 7u) << 4);
}
__device__ __forceinline__ void pk2(float x, float y, uint32_t& hi, uint32_t& lo) {
    __nv_bfloat16 hx = __float2bfloat16(x), hy = __float2bfloat16(y);
    hi = ((uint32_t)*(uint16_t*)&hy << 16) | *(uint16_t*)&hx;
    __nv_bfloat16 lx = __float2bfloat16(x - __bfloat162float(hx));
    __nv_bfloat16 ly = __float2bfloat16(y - __bfloat162float(hy));
    lo = ((uint32_t)*(uint16_t*)&ly << 16) | *(uint16_t*)&lx;
}

// ---------------------------------------------------------------------------
// Split-bf16 tensor-core GEMM: C[M,N] = A[M,4096] @ B[4096,N]
// 3-pass (AhBh + AhBl + AlBh). CTA 128x256, BK=64, 2-stage cp.async.
// 8 warps = 2m x 4n of 64x64 warp tiles. smem/stage: A 32KB + B 64KB.
// ---------------------------------------------------------------------------
#define GEMM_SMEM 196608

__global__ void __launch_bounds__(256) gemm_bf16s(
    const __nv_bfloat16* __restrict__ Ah, const __nv_bfloat16* __restrict__ Al,
    const __nv_bfloat16* __restrict__ Bh, const __nv_bfloat16* __restrict__ Bl,
    float* __restrict__ Cf,
    __nv_bfloat16* __restrict__ Oh, __nv_bfloat16* __restrict__ Ol, int N)
{
    extern __shared__ __align__(1024) char smg[];
    const uint32_t sb = su32(smg);
    const int tid = threadIdx.x, w = tid >> 5, l = tid & 31;
    const int n0 = blockIdx.x * 256, m0 = blockIdx.y * 128;
    const int wm = (w & 1) * 64, wn = (w >> 1) * 64;

    auto loadChunk = [&](int c) {
        const uint32_t st = sb + (uint32_t)(c & 1) * 98304;
        const int k0 = c * 64;
        #pragma unroll
        for (int t = 0; t < 8; t++) {                 // A: hi (t<4) then lo
            int j = tid + (t & 3) * 256;              // 0..1023
            int r = j >> 3, c16 = j & 7;
            uint32_t o = swz128((uint32_t)(r * 128 + c16 * 16));
            const __nv_bfloat16* src = (t < 4 ? Ah : Al) +
                (size_t)(m0 + r) * GK + k0 + c16 * 8;
            cp16(st + (t < 4 ? 0u : 16384u) + o, src);
        }
        #pragma unroll
        for (int t = 0; t < 16; t++) {                // B: hi (t<8) then lo
            int j = tid + (t & 7) * 256;              // 0..2047
            int r = j >> 5, c16 = j & 31;
            uint32_t o = swz512((uint32_t)(r * 512 + c16 * 16));
            const __nv_bfloat16* src = (t < 8 ? Bh : Bl) +
                (size_t)(k0 + r) * N + n0 + c16 * 8;
            cp16(st + (t < 8 ? 32768u : 65536u) + o, src);
        }
        CP_COMMIT();
    };

    float acc[4][8][4];
    #pragma unroll
    for (int mf = 0; mf < 4; mf++)
        #pragma unroll
        for (int nb = 0; nb < 8; nb++)
            { acc[mf][nb][0]=0.f; acc[mf][nb][1]=0.f; acc[mf][nb][2]=0.f; acc[mf][nb][3]=0.f; }

    loadChunk(0);

    const int NC = GK / 64;
    for (int c = 0; c < NC; c++) {
        if (c + 1 < NC) {
            loadChunk(c + 1);
            asm volatile("cp.async.wait_group 1;\n");
        } else {
            asm volatile("cp.async.wait_group 0;\n");
        }
        __syncthreads();
        const uint32_t st = sb + (uint32_t)(c & 1) * 98304;

        #pragma unroll
        for (int ks = 0; ks < 4; ks++) {
            uint32_t ah[4][4], alr[4][4];
            #pragma unroll
            for (int mf = 0; mf < 4; mf++) {
                uint32_t base = (uint32_t)((wm + mf * 16 + (l & 15)) * 128 +
                                           ks * 32 + ((l & 16) ? 16 : 0));
                LDSM_X4(ah[mf],  st + swz128(base));
                LDSM_X4(alr[mf], st + 16384 + swz128(base));
            }
            #pragma unroll
            for (int g = 0; g < 4; g++) {
                uint32_t br = (uint32_t)(ks * 16 + (l & 7) + ((l & 8) ? 8 : 0));
                uint32_t bc = (uint32_t)((wn + g * 16) * 2 + ((l & 16) ? 16 : 0));
                uint32_t badr = st + 32768 + swz512(br * 512 + bc);
                uint32_t bh[4], bl[4];
                LDSM_X4T(bh, badr);
                LDSM_X4T(bl, badr + 32768);
                #pragma unroll
                for (int mf = 0; mf < 4; mf++) {
                    MMA4(acc[mf][2*g],   ah[mf],  bh[0], bh[1]);
                    MMA4(acc[mf][2*g+1], ah[mf],  bh[2], bh[3]);
                    MMA4(acc[mf][2*g],   ah[mf],  bl[0], bl[1]);
                    MMA4(acc[mf][2*g+1], ah[mf],  bl[2], bl[3]);
                    MMA4(acc[mf][2*g],   alr[mf], bh[0], bh[1]);
                    MMA4(acc[mf][2*g+1], alr[mf], bh[2], bh[3]);
                }
            }
        }
        __syncthreads();
    }

    // epilogue
    #pragma unroll
    for (int mf = 0; mf < 4; mf++) {
        int r0 = m0 + wm + mf * 16 + (l >> 2);
        #pragma unroll
        for (int nb = 0; nb < 8; nb++) {
            int cc = n0 + wn + nb * 8 + (l & 3) * 2;
            if (Cf) {
                *(float2*)(Cf + (size_t)r0 * N + cc) =
                    make_float2(acc[mf][nb][0], acc[mf][nb][1]);
                *(float2*)(Cf + (size_t)(r0 + 8) * N + cc) =
                    make_float2(acc[mf][nb][2], acc[mf][nb][3]);
            } else {
                uint32_t hi, lo;
                pk2(acc[mf][nb][0], acc[mf][nb][1], hi, lo);
                *(uint32_t*)(Oh + (size_t)r0 * N + cc) = hi;
                *(uint32_t*)(Ol + (size_t)r0 * N + cc) = lo;
                pk2(acc[mf][nb][2], acc[mf][nb][3], hi, lo);
                *(uint32_t*)(Oh + (size_t)(r0 + 8) * N + cc) = hi;
                *(uint32_t*)(Ol + (size_t)(r0 + 8) * N + cc) = lo;
            }
        }
    }
}

// ---------------------------------------------------------------------------
// conversions & RoPE
// ---------------------------------------------------------------------------
__global__ void cvt_hl(const float* __restrict__ X,
                       __nv_bfloat16* __restrict__ H, __nv_bfloat16* __restrict__ L, int n)
{
    int i = blockIdx.x * 256 + threadIdx.x;
    if (i >= n) return;
    float v = X[i];
    __nv_bfloat16 h = __float2bfloat16(v);
    H[i] = h;
    L[i] = __float2bfloat16(v - __bfloat162float(h));
}

__global__ void rope_table_k()
{
    int idx = blockIdx.x * blockDim.x + threadIdx.x;
    if (idx >= SS * 64) return;
    int pos = idx >> 6;
    int i   = idx & 63;
    float invf = (float)pow(10000.0, -((double)i) / 64.0);
    float angf = (float)pos * invf;
    double ang = (double)angf;
    g_cos[idx] = (float)cos(ang);
    g_sin[idx] = (float)sin(ang);
}

__global__ void rope_split_k(const float* __restrict__ X,
                             __nv_bfloat16* __restrict__ H,
                             __nv_bfloat16* __restrict__ L,
                             int nh, float scale)
{
    int idx = blockIdx.x * blockDim.x + threadIdx.x;
    int total = MR * nh * 64;
    if (idx >= total) return;
    int half = idx & 63;
    int h    = (idx >> 6) % nh;
    int r    = idx / (64 * nh);
    int s    = r % SS;
    size_t base = (size_t)r * nh * HD + (size_t)h * HD;
    float c  = g_cos[s * 64 + half];
    float sn = g_sin[s * 64 + half];
    float x1 = X[base + half];
    float x2 = X[base + half + 64];
    float y1 = (x1 * c - x2 * sn) * scale;
    float y2 = (x2 * c + x1 * sn) * scale;
    __nv_bfloat16 h1 = __float2bfloat16(y1);
    __nv_bfloat16 h2 = __float2bfloat16(y2);
    H[base + half]      = h1;
    H[base + half + 64] = h2;
    L[base + half]      = __float2bfloat16(y1 - __bfloat162float(h1));
    L[base + half + 64] = __float2bfloat16(y2 - __bfloat162float(h2));
}

// ---------------------------------------------------------------------------
// FlashAttention-2 mma.sync bf16 split (proven R7 kernel, unchanged).
// ---------------------------------------------------------------------------
#define ATT_SMEM 196608

__global__ void __launch_bounds__(256) attn_mma()
{
    extern __shared__ __align__(1024) char smdyn[];
    const int qb = blockIdx.x, h = blockIdx.y, b = blockIdx.z;
    const int kvh = h / GRP;
    const int tid = threadIdx.x, w = tid >> 5, l = tid & 31;
    const uint32_t sb = su32(smdyn);
    const uint32_t Qh_s = sb;
    const uint32_t KV0  = sb + 65536;

    {
        const __nv_bfloat16* qh = g_Qh + (size_t)(b * SS + qb * 128) * HID + h * HD;
        const __nv_bfloat16* ql = g_Ql + (size_t)(b * SS + qb * 128) * HID + h * HD;
        #pragma unroll
        for (int t = 0; t < 8; t++) {
            int j = tid + t * 256;
            int r = j >> 4, c = j & 15;
            uint32_t o = swz256((uint32_t)(r * 256 + c * 16));
            cp16(Qh_s + o,         (const void*)(qh + (size_t)r * HID + c * 8));
            cp16(Qh_s + 32768 + o, (const void*)(ql + (size_t)r * HID + c * 8));
        }
        CP_COMMIT();
    }

    const int NT = 2 * qb + 2;
    auto loadKV = [&](int kt) {
        const uint32_t st = KV0 + (uint32_t)(kt & 1) * 65536;
        const size_t rb = (size_t)(b * SS + kt * 64) * KVD + kvh * HD;
        #pragma unroll
        for (int t = 0; t < 4; t++) {
            int j = tid + t * 256;
            int r = j >> 4, c = j & 15;
            uint32_t o = swz256((uint32_t)(r * 256 + c * 16));
            size_t g = rb + (size_t)r * KVD + c * 8;
            cp16(st +         o, (const void*)(g_Kh + g));
            cp16(st + 16384 + o, (const void*)(g_Kl + g));
            cp16(st + 32768 + o, (const void*)(g_Vh + g));
            cp16(st + 49152 + o, (const void*)(g_Vl + g));
        }
        CP_COMMIT();
    };
    loadKV(0);

    const int m0 = w * 16;
    const int qg0 = qb * 128 + m0 + (l >> 2);
    float O[16][4];
    #pragma unroll
    for (int f = 0; f < 16; f++)
        { O[f][0] = 0.f; O[f][1] = 0.f; O[f][2] = 0.f; O[f][3] = 0.f; }
    float mr0 = -1e30f, mr1 = -1e30f, sl0 = 0.f, sl1 = 0.f;

    for (int kt = 0; kt < NT; kt++) {
        if (kt + 1 < NT) {
            loadKV(kt + 1);
            asm volatile("cp.async.wait_group 1;\n");
        } else {
            asm volatile("cp.async.wait_group 0;\n");
        }
        __syncthreads();

        const uint32_t st = KV0 + (uint32_t)(kt & 1) * 65536;

        float s[8][4];
        #pragma unroll
        for (int nb = 0; nb < 8; nb++)
            { s[nb][0] = 0.f; s[nb][1] = 0.f; s[nb][2] = 0.f; s[nb][3] = 0.f; }

        #pragma unroll
        for (int ks = 0; ks < 8; ks++) {
            uint32_t aQh[4], aQl[4];
            uint32_t aaddr = Qh_s + swz256(
                (uint32_t)((m0 + (l & 15)) * 256 + ks * 32 + ((l & 16) ? 16 : 0)));
            LDSM_X4(aQh, aaddr);
            LDSM_X4(aQl, aaddr + 32768);
            #pragma unroll
            for (int nb2 = 0; nb2 < 4; nb2++) {
                uint32_t brow = (uint32_t)(nb2 * 16 + (l & 7) + ((l & 16) ? 8 : 0));
                uint32_t baddr = st + swz256(brow * 256 + ks * 32 + ((l & 8) ? 16 : 0));
                uint32_t bh[4], bl[4];
                LDSM_X4(bh, baddr);
                LDSM_X4(bl, baddr + 16384);
                MMA4(s[2*nb2],   aQh, bh[0], bh[1]);
                MMA4(s[2*nb2+1], aQh, bh[2], bh[3]);
                MMA4(s[2*nb2],   aQh, bl[0], bl[1]);
                MMA4(s[2*nb2+1], aQh, bl[2], bl[3]);
                MMA4(s[2*nb2],   aQl, bh[0], bh[1]);
                MMA4(s[2*nb2+1], aQl, bh[2], bh[3]);
            }
        }

        const int kgb = kt * 64 + (l & 3) * 2;
        float mx0 = -1e30f, mx1 = -1e30f;
        #pragma unroll
        for (int nb = 0; nb < 8; nb++) {
            int kg = kgb + nb * 8;
            if (kg     > qg0)     s[nb][0] = -1e30f;
            if (kg + 1 > qg0)     s[nb][1] = -1e30f;
            if (kg     > qg0 + 8) s[nb][2] = -1e30f;
            if (kg + 1 > qg0 + 8) s[nb][3] = -1e30f;
            mx0 = fmaxf(mx0, fmaxf(s[nb][0], s[nb][1]));
            mx1 = fmaxf(mx1, fmaxf(s[nb][2], s[nb][3]));
        }
        mx0 = fmaxf(mx0, __shfl_xor_sync(0xffffffffu, mx0, 1));
        mx0 = fmaxf(mx0, __shfl_xor_sync(0xffffffffu, mx0, 2));
        mx1 = fmaxf(mx1, __shfl_xor_sync(0xffffffffu, mx1, 1));
        mx1 = fmaxf(mx1, __shfl_xor_sync(0xffffffffu, mx1, 2));

        float mn0 = fmaxf(mr0, mx0), mn1 = fmaxf(mr1, mx1);
        float al0 = __expf(mr0 - mn0), al1 = __expf(mr1 - mn1);
        mr0 = mn0; mr1 = mn1;
        float sum0 = 0.f, sum1 = 0.f;
        #pragma unroll
        for (int nb = 0; nb < 8; nb++) {
            s[nb][0] = __expf(s[nb][0] - mn0);
            s[nb][1] = __expf(s[nb][1] - mn0);
            s[nb][2] = __expf(s[nb][2] - mn1);
            s[nb][3] = __expf(s[nb][3] - mn1);
            sum0 += s[nb][0] + s[nb][1];
            sum1 += s[nb][2] + s[nb][3];
        }
        sum0 += __shfl_xor_sync(0xffffffffu, sum0, 1);
        sum0 += __shfl_xor_sync(0xffffffffu, sum0, 2);
        sum1 += __shfl_xor_sync(0xffffffffu, sum1, 1);
        sum1 += __shfl_xor_sync(0xffffffffu, sum1, 2);
        sl0 = sl0 * al0 + sum0;
        sl1 = sl1 * al1 + sum1;
        #pragma unroll
        for (int f = 0; f < 16; f++) {
            O[f][0] *= al0; O[f][1] *= al0; O[f][2] *= al1; O[f][3] *= al1;
        }

        #pragma unroll
        for (int j = 0; j < 4; j++) {
            uint32_t ph[4], pl[4];
            pk2(s[2*j][0],   s[2*j][1],   ph[0], pl[0]);
            pk2(s[2*j][2],   s[2*j][3],   ph[1], pl[1]);
            pk2(s[2*j+1][0], s[2*j+1][1], ph[2], pl[2]);
            pk2(s[2*j+1][2], s[2*j+1][3], ph[3], pl[3]);
            uint32_t vrow = (uint32_t)(j * 16 + (l & 7) + ((l & 8) ? 8 : 0));
            #pragma unroll
            for (int nb2 = 0; nb2 < 8; nb2++) {
                uint32_t vaddr = st + 32768 +
                    swz256(vrow * 256 + nb2 * 32 + ((l & 16) ? 16 : 0));
                uint32_t vh[4], vl[4];
                LDSM_X4T(vh, vaddr);
                LDSM_X4T(vl, vaddr + 16384);
                MMA4(O[2*nb2],   ph, vh[0], vh[1]);
                MMA4(O[2*nb2+1], ph, vh[2], vh[3]);
                MMA4(O[2*nb2],   ph, vl[0], vl[1]);
                MMA4(O[2*nb2+1], ph, vl[2], vl[3]);
                MMA4(O[2*nb2],   pl, vh[0], vh[1]);
                MMA4(O[2*nb2+1], pl, vh[2], vh[3]);
            }
        }
        __syncthreads();
    }

    const float i0 = 1.0f / sl0, i1 = 1.0f / sl1;
    size_t base0 = (size_t)(b * SS + qg0) * HID + (size_t)h * HD;
    size_t base1 = base0 + (size_t)8 * HID;
    #pragma unroll
    for (int nb = 0; nb < 16; nb++) {
        int col = nb * 8 + (l & 3) * 2;
        uint32_t hi, lo;
        pk2(O[nb][0] * i0, O[nb][1] * i0, hi, lo);
        *(uint32_t*)(g_Ath + base0 + col) = hi;
        *(uint32_t*)(g_Atl + base0 + col) = lo;
        pk2(O[nb][2] * i1, O[nb][3] * i1, hi, lo);
        *(uint32_t*)(g_Ath + base1 + col) = hi;
        *(uint32_t*)(g_Atl + base1 + col) = lo;
    }
}

// ---------------------------------------------------------------------------
extern "C" void kernel_launch(void* const* d_in, const int* in_sizes, int n_in,
                              void* d_out, int out_size)
{
    (void)in_sizes; (void)n_in; (void)out_size;
    const float* x  = (const float*)d_in[0];
    const float* Wq = (const float*)d_in[1];
    const float* Wk = (const float*)d_in[2];
    const float* Wv = (const float*)d_in[3];
    const float* Wo = (const float*)d_in[4];
    float* out = (float*)d_out;

    float *Qp, *Kp;
    __nv_bfloat16 *xh, *xl, *wqh, *wql, *wkh, *wkl, *wvh, *wvl, *woh, *wol;
    __nv_bfloat16 *qh, *ql, *kh, *kl, *vh, *vl, *ath, *atl;
    cudaGetSymbolAddress((void**)&Qp, g_Q);
    cudaGetSymbolAddress((void**)&Kp, g_K);
    cudaGetSymbolAddress((void**)&xh, g_xh);   cudaGetSymbolAddress((void**)&xl, g_xl);
    cudaGetSymbolAddress((void**)&wqh, g_Wqh); cudaGetSymbolAddress((void**)&wql, g_Wql);
    cudaGetSymbolAddress((void**)&wkh, g_Wkh); cudaGetSymbolAddress((void**)&wkl, g_Wkl);
    cudaGetSymbolAddress((void**)&wvh, g_Wvh); cudaGetSymbolAddress((void**)&wvl, g_Wvl);
    cudaGetSymbolAddress((void**)&woh, g_Woh); cudaGetSymbolAddress((void**)&wol, g_Wol);
    cudaGetSymbolAddress((void**)&qh, g_Qh);   cudaGetSymbolAddress((void**)&ql, g_Ql);
    cudaGetSymbolAddress((void**)&kh, g_Kh);   cudaGetSymbolAddress((void**)&kl, g_Kl);
    cudaGetSymbolAddress((void**)&vh, g_Vh);   cudaGetSymbolAddress((void**)&vl, g_Vl);
    cudaGetSymbolAddress((void**)&ath, g_Ath); cudaGetSymbolAddress((void**)&atl, g_Atl);

    cudaFuncSetAttribute(gemm_bf16s, cudaFuncAttributeMaxDynamicSharedMemorySize, GEMM_SMEM);
    cudaFuncSetAttribute(attn_mma, cudaFuncAttributeMaxDynamicSharedMemorySize, ATT_SMEM);

    rope_table_k<<<(SS * 64 + 255) / 256, 256>>>();

    cvt_hl<<<(MR * HID + 255) / 256, 256>>>(x,  xh,  xl,  MR * HID);
    cvt_hl<<<(HID * HID + 255) / 256, 256>>>(Wq, wqh, wql, HID * HID);
    cvt_hl<<<(HID * KVD + 255) / 256, 256>>>(Wk, wkh, wkl, HID * KVD);
    cvt_hl<<<(HID * KVD + 255) / 256, 256>>>(Wv, wvh, wvl, HID * KVD);
    cvt_hl<<<(HID * HID + 255) / 256, 256>>>(Wo, woh, wol, HID * HID);

    gemm_bf16s<<<dim3(HID / 256, MR / 128), 256, GEMM_SMEM>>>(
        xh, xl, wqh, wql, Qp, nullptr, nullptr, HID);
    gemm_bf16s<<<dim3(KVD / 256, MR / 128), 256, GEMM_SMEM>>>(
        xh, xl, wkh, wkl, Kp, nullptr, nullptr, KVD);
    gemm_bf16s<<<dim3(KVD / 256, MR / 128), 256, GEMM_SMEM>>>(
        xh, xl, wvh, wvl, nullptr, vh, vl, KVD);

    const float scale = 0.08838834764831845f;   // 1/sqrt(128)
    rope_split_k<<<(MR * NHQ  * 64 + 255) / 256, 256>>>(Qp, qh, ql, NHQ, scale);
    rope_split_k<<<(MR * NHKV * 64 + 255) / 256, 256>>>(Kp, kh, kl, NHKV, 1.0f);

    attn_mma<<<dim3(SS / 128, NHQ, BB), 256, ATT_SMEM>>>();

    gemm_bf16s<<<dim3(HID / 256, MR / 128), 256, GEMM_SMEM>>>(
        ath, atl, woh, wol, out, nullptr, nullptr, HID);
}

// round 13
// speedup vs baseline: 3.5729x; 1.0561x over previous
#include <cuda_runtime.h>
#include <cuda_bf16.h>
#include <math.h>
#include <stdint.h>

#define BB 2
#define SS 2048
#define HID 4096
#define NHQ 32
#define NHKV 8
#define HD 128
#define MR (BB*SS)          // 4096 rows
#define KVD (NHKV*HD)       // 1024
#define GRP (NHQ/NHKV)      // 4
#define GK 4096             // all GEMMs have K=4096

// ---------------- scratch (__device__ globals) ------------------------------
__device__ float g_Q[MR*HID];
__device__ float g_K[MR*KVD];
__device__ float g_cos[SS*(HD/2)];
__device__ float g_sin[SS*(HD/2)];
__device__ __nv_bfloat16 g_xh[MR*HID],  g_xl[MR*HID];
__device__ __nv_bfloat16 g_Wqh[HID*HID], g_Wql[HID*HID];   // [K,N] row-major
__device__ __nv_bfloat16 g_Wkh[HID*KVD], g_Wkl[HID*KVD];
__device__ __nv_bfloat16 g_Wvh[HID*KVD], g_Wvl[HID*KVD];
__device__ __nv_bfloat16 g_Woh[HID*HID], g_Wol[HID*HID];
__device__ __nv_bfloat16 g_Qh[MR*HID], g_Ql[MR*HID];
__device__ __nv_bfloat16 g_Kh[MR*KVD], g_Kl[MR*KVD];
__device__ __nv_bfloat16 g_Vh[MR*KVD], g_Vl[MR*KVD];
__device__ __nv_bfloat16 g_Ath[MR*HID], g_Atl[MR*HID];

// ---------------- PTX helpers (portable sm_80-era ops) ----------------------
__device__ __forceinline__ uint32_t su32(const void* p) {
    uint32_t a;
    asm("{ .reg .u64 t; cvta.to.shared.u64 t, %1; cvt.u32.u64 %0, t; }"
        : "=r"(a) : "l"(p));
    return a;
}
__device__ __forceinline__ void cp16(uint32_t sa, const void* g) {
    asm volatile("cp.async.cg.shared.global [%0], [%1], 16;\n" :: "r"(sa), "l"(g));
}
#define CP_COMMIT() asm volatile("cp.async.commit_group;\n")
#define LDSM_X4(r, a) \
    asm volatile("ldmatrix.sync.aligned.m8n8.x4.shared.b16 {%0,%1,%2,%3}, [%4];" \
        : "=r"((r)[0]), "=r"((r)[1]), "=r"((r)[2]), "=r"((r)[3]) : "r"(a))
#define LDSM_X4T(r, a) \
    asm volatile("ldmatrix.sync.aligned.m8n8.x4.trans.shared.b16 {%0,%1,%2,%3}, [%4];" \
        : "=r"((r)[0]), "=r"((r)[1]), "=r"((r)[2]), "=r"((r)[3]) : "r"(a))
#define MMA4(d, a, b0, b1) \
    asm volatile("mma.sync.aligned.m16n8k16.row.col.f32.bf16.bf16.f32 " \
        "{%0,%1,%2,%3},{%4,%5,%6,%7},{%8,%9},{%0,%1,%2,%3};" \
        : "+f"((d)[0]), "+f"((d)[1]), "+f"((d)[2]), "+f"((d)[3]) \
        : "r"((a)[0]), "r"((a)[1]), "r"((a)[2]), "r"((a)[3]), "r"(b0), "r"(b1))

__device__ __forceinline__ uint32_t swz256(uint32_t o) {   // 256B rows
    return o ^ (((o >> 8) & 7u) << 4);
}
__device__ __forceinline__ uint32_t swz128(uint32_t o) {   // 128B rows
    return o ^ (((o >> 7) & 7u) << 4);
}
__device__ __forceinline__ void pk2(float x, float y, uint32_t& hi, uint32_t& lo) {
    __nv_bfloat16 hx = __float2bfloat16(x), hy = __float2bfloat16(y);
    hi = ((uint32_t)*(uint16_t*)&hy << 16) | *(uint16_t*)&hx;
    __nv_bfloat16 lx = __float2bfloat16(x - __bfloat162float(hx));
    __nv_bfloat16 ly = __float2bfloat16(y - __bfloat162float(hy));
    lo = ((uint32_t)*(uint16_t*)&ly << 16) | *(uint16_t*)&lx;
}

// ---------------------------------------------------------------------------
// Split-bf16 tensor-core GEMM: C[M,N] = A[M,4096] @ B[4096,N]
// 3-pass (AhBh + AhBl + AlBh). CTA 128x128, BK=64, THREE-stage cp.async.
// 8 warps = 2m x 4n of 64x32 warp tiles. stage = 64KB (Ah,Al,Bh,Bl 16KB each).
// ---------------------------------------------------------------------------
#define GEMM_SMEM 196608

__global__ void __launch_bounds__(256) gemm_bf16s(
    const __nv_bfloat16* __restrict__ Ah, const __nv_bfloat16* __restrict__ Al,
    const __nv_bfloat16* __restrict__ Bh, const __nv_bfloat16* __restrict__ Bl,
    float* __restrict__ Cf,
    __nv_bfloat16* __restrict__ Oh, __nv_bfloat16* __restrict__ Ol, int N)
{
    extern __shared__ __align__(1024) char smg[];
    const uint32_t sb = su32(smg);
    const int tid = threadIdx.x, w = tid >> 5, l = tid & 31;
    const int n0 = blockIdx.x * 128, m0 = blockIdx.y * 128;
    const int wm = (w & 1) * 64, wn = (w >> 1) * 32;

    auto loadChunk = [&](int c, int stg) {
        const uint32_t st = sb + (uint32_t)stg * 65536;
        const int k0 = c * 64;
        #pragma unroll
        for (int t = 0; t < 4; t++) {                 // A: [128 m][64 k], 128B rows
            int j = tid + t * 256;
            int r = j >> 3, cc = j & 7;
            uint32_t o = swz128((uint32_t)(r * 128 + cc * 16));
            size_t g = (size_t)(m0 + r) * GK + k0 + cc * 8;
            cp16(st + o,         (const void*)(Ah + g));
            cp16(st + 16384 + o, (const void*)(Al + g));
        }
        #pragma unroll
        for (int t = 0; t < 4; t++) {                 // B: [64 k][128 n], 256B rows
            int j = tid + t * 256;
            int r = j >> 4, cc = j & 15;
            uint32_t o = swz256((uint32_t)(r * 256 + cc * 16));
            size_t g = (size_t)(k0 + r) * N + n0 + cc * 8;
            cp16(st + 32768 + o, (const void*)(Bh + g));
            cp16(st + 49152 + o, (const void*)(Bl + g));
        }
        CP_COMMIT();
    };

    float acc[4][4][4];
    #pragma unroll
    for (int mf = 0; mf < 4; mf++)
        #pragma unroll
        for (int nf = 0; nf < 4; nf++)
            { acc[mf][nf][0]=0.f; acc[mf][nf][1]=0.f; acc[mf][nf][2]=0.f; acc[mf][nf][3]=0.f; }

    loadChunk(0, 0);
    loadChunk(1, 1);

    const int NC = GK / 64;
    int stg = 0;
    for (int c = 0; c < NC; c++) {
        if (c + 1 < NC) {
            asm volatile("cp.async.wait_group 1;\n");    // chunk c landed
        } else {
            asm volatile("cp.async.wait_group 0;\n");
        }
        __syncthreads();                                 // all warps done with stage (c+2)%3
        int nstg = stg + 2; if (nstg >= 3) nstg -= 3;
        if (c + 2 < NC) loadChunk(c + 2, nstg);

        const uint32_t st = sb + (uint32_t)stg * 65536;
        #pragma unroll
        for (int ks = 0; ks < 4; ks++) {
            uint32_t ah[4][4], alr[4][4];
            #pragma unroll
            for (int mf = 0; mf < 4; mf++) {
                uint32_t adr = st + swz128((uint32_t)(
                    (wm + mf * 16 + (l & 15)) * 128 + ks * 32 + ((l & 16) ? 16 : 0)));
                LDSM_X4(ah[mf], adr);
                LDSM_X4(alr[mf], adr + 16384);
            }
            #pragma unroll
            for (int g = 0; g < 2; g++) {
                uint32_t br = (uint32_t)(ks * 16 + (l & 7) + ((l & 8) ? 8 : 0));
                uint32_t bc = (uint32_t)((wn + g * 16) * 2 + ((l & 16) ? 16 : 0));
                uint32_t badr = st + 32768 + swz256(br * 256 + bc);
                uint32_t bh[4], bl[4];
                LDSM_X4T(bh, badr);
                LDSM_X4T(bl, badr + 16384);
                #pragma unroll
                for (int mf = 0; mf < 4; mf++) {
                    MMA4(acc[mf][2*g],   ah[mf],  bh[0], bh[1]);
                    MMA4(acc[mf][2*g+1], ah[mf],  bh[2], bh[3]);
                    MMA4(acc[mf][2*g],   ah[mf],  bl[0], bl[1]);
                    MMA4(acc[mf][2*g+1], ah[mf],  bl[2], bl[3]);
                    MMA4(acc[mf][2*g],   alr[mf], bh[0], bh[1]);
                    MMA4(acc[mf][2*g+1], alr[mf], bh[2], bh[3]);
                }
            }
        }
        if (++stg >= 3) stg -= 3;
    }

    // epilogue
    #pragma unroll
    for (int mf = 0; mf < 4; mf++) {
        int r0 = m0 + wm + mf * 16 + (l >> 2);
        #pragma unroll
        for (int nf = 0; nf < 4; nf++) {
            int cc = n0 + wn + nf * 8 + (l & 3) * 2;
            if (Cf) {
                *(float2*)(Cf + (size_t)r0 * N + cc) =
                    make_float2(acc[mf][nf][0], acc[mf][nf][1]);
                *(float2*)(Cf + (size_t)(r0 + 8) * N + cc) =
                    make_float2(acc[mf][nf][2], acc[mf][nf][3]);
            } else {
                uint32_t hi, lo;
                pk2(acc[mf][nf][0], acc[mf][nf][1], hi, lo);
                *(uint32_t*)(Oh + (size_t)r0 * N + cc) = hi;
                *(uint32_t*)(Ol + (size_t)r0 * N + cc) = lo;
                pk2(acc[mf][nf][2], acc[mf][nf][3], hi, lo);
                *(uint32_t*)(Oh + (size_t)(r0 + 8) * N + cc) = hi;
                *(uint32_t*)(Ol + (size_t)(r0 + 8) * N + cc) = lo;
            }
        }
    }
}

// ---------------------------------------------------------------------------
// conversions (float4-vectorized) & RoPE
// ---------------------------------------------------------------------------
__global__ void cvt_hl(const float* __restrict__ X,
                       __nv_bfloat16* __restrict__ H, __nv_bfloat16* __restrict__ L, int n4)
{
    int i = blockIdx.x * 256 + threadIdx.x;
    if (i >= n4) return;
    float4 v = *(const float4*)(X + (size_t)i * 4);
    uint32_t h01, l01, h23, l23;
    pk2(v.x, v.y, h01, l01);
    pk2(v.z, v.w, h23, l23);
    *(uint2*)(H + (size_t)i * 4) = make_uint2(h01, h23);
    *(uint2*)(L + (size_t)i * 4) = make_uint2(l01, l23);
}

__global__ void rope_table_k()
{
    int idx = blockIdx.x * blockDim.x + threadIdx.x;
    if (idx >= SS * 64) return;
    int pos = idx >> 6;
    int i   = idx & 63;
    float invf = (float)pow(10000.0, -((double)i) / 64.0);
    float angf = (float)pos * invf;
    double ang = (double)angf;
    g_cos[idx] = (float)cos(ang);
    g_sin[idx] = (float)sin(ang);
}

__global__ void rope_split_k(const float* __restrict__ X,
                             __nv_bfloat16* __restrict__ H,
                             __nv_bfloat16* __restrict__ L,
                             int nh, float scale)
{
    int idx = blockIdx.x * blockDim.x + threadIdx.x;
    int total = MR * nh * 64;
    if (idx >= total) return;
    int half = idx & 63;
    int h    = (idx >> 6) % nh;
    int r    = idx / (64 * nh);
    int s    = r % SS;
    size_t base = (size_t)r * nh * HD + (size_t)h * HD;
    float c  = g_cos[s * 64 + half];
    float sn = g_sin[s * 64 + half];
    float x1 = X[base + half];
    float x2 = X[base + half + 64];
    float y1 = (x1 * c - x2 * sn) * scale;
    float y2 = (x2 * c + x1 * sn) * scale;
    __nv_bfloat16 h1 = __float2bfloat16(y1);
    __nv_bfloat16 h2 = __float2bfloat16(y2);
    H[base + half]      = h1;
    H[base + half + 64] = h2;
    L[base + half]      = __float2bfloat16(y1 - __bfloat162float(h1));
    L[base + half + 64] = __float2bfloat16(y2 - __bfloat162float(h2));
}

// ---------------------------------------------------------------------------
// FlashAttention-2 mma.sync bf16 split (proven R7 kernel, unchanged).
// ---------------------------------------------------------------------------
#define ATT_SMEM 196608

__global__ void __launch_bounds__(256) attn_mma()
{
    extern __shared__ __align__(1024) char smdyn[];
    const int qb = blockIdx.x, h = blockIdx.y, b = blockIdx.z;
    const int kvh = h / GRP;
    const int tid = threadIdx.x, w = tid >> 5, l = tid & 31;
    const uint32_t sb = su32(smdyn);
    const uint32_t Qh_s = sb;
    const uint32_t KV0  = sb + 65536;

    {
        const __nv_bfloat16* qh = g_Qh + (size_t)(b * SS + qb * 128) * HID + h * HD;
        const __nv_bfloat16* ql = g_Ql + (size_t)(b * SS + qb * 128) * HID + h * HD;
        #pragma unroll
        for (int t = 0; t < 8; t++) {
            int j = tid + t * 256;
            int r = j >> 4, c = j & 15;
            uint32_t o = swz256((uint32_t)(r * 256 + c * 16));
            cp16(Qh_s + o,         (const void*)(qh + (size_t)r * HID + c * 8));
            cp16(Qh_s + 32768 + o, (const void*)(ql + (size_t)r * HID + c * 8));
        }
        CP_COMMIT();
    }

    const int NT = 2 * qb + 2;
    auto loadKV = [&](int kt) {
        const uint32_t st = KV0 + (uint32_t)(kt & 1) * 65536;
        const size_t rb = (size_t)(b * SS + kt * 64) * KVD + kvh * HD;
        #pragma unroll
        for (int t = 0; t < 4; t++) {
            int j = tid + t * 256;
            int r = j >> 4, c = j & 15;
            uint32_t o = swz256((uint32_t)(r * 256 + c * 16));
            size_t g = rb + (size_t)r * KVD + c * 8;
            cp16(st +         o, (const void*)(g_Kh + g));
            cp16(st + 16384 + o, (const void*)(g_Kl + g));
            cp16(st + 32768 + o, (const void*)(g_Vh + g));
            cp16(st + 49152 + o, (const void*)(g_Vl + g));
        }
        CP_COMMIT();
    };
    loadKV(0);

    const int m0 = w * 16;
    const int qg0 = qb * 128 + m0 + (l >> 2);
    float O[16][4];
    #pragma unroll
    for (int f = 0; f < 16; f++)
        { O[f][0] = 0.f; O[f][1] = 0.f; O[f][2] = 0.f; O[f][3] = 0.f; }
    float mr0 = -1e30f, mr1 = -1e30f, sl0 = 0.f, sl1 = 0.f;

    for (int kt = 0; kt < NT; kt++) {
        if (kt + 1 < NT) {
            loadKV(kt + 1);
            asm volatile("cp.async.wait_group 1;\n");
        } else {
            asm volatile("cp.async.wait_group 0;\n");
        }
        __syncthreads();

        const uint32_t st = KV0 + (uint32_t)(kt & 1) * 65536;

        float s[8][4];
        #pragma unroll
        for (int nb = 0; nb < 8; nb++)
            { s[nb][0] = 0.f; s[nb][1] = 0.f; s[nb][2] = 0.f; s[nb][3] = 0.f; }

        #pragma unroll
        for (int ks = 0; ks < 8; ks++) {
            uint32_t aQh[4], aQl[4];
            uint32_t aaddr = Qh_s + swz256(
                (uint32_t)((m0 + (l & 15)) * 256 + ks * 32 + ((l & 16) ? 16 : 0)));
            LDSM_X4(aQh, aaddr);
            LDSM_X4(aQl, aaddr + 32768);
            #pragma unroll
            for (int nb2 = 0; nb2 < 4; nb2++) {
                uint32_t brow = (uint32_t)(nb2 * 16 + (l & 7) + ((l & 16) ? 8 : 0));
                uint32_t baddr = st + swz256(brow * 256 + ks * 32 + ((l & 8) ? 16 : 0));
                uint32_t bh[4], bl[4];
                LDSM_X4(bh, baddr);
                LDSM_X4(bl, baddr + 16384);
                MMA4(s[2*nb2],   aQh, bh[0], bh[1]);
                MMA4(s[2*nb2+1], aQh, bh[2], bh[3]);
                MMA4(s[2*nb2],   aQh, bl[0], bl[1]);
                MMA4(s[2*nb2+1], aQh, bl[2], bl[3]);
                MMA4(s[2*nb2],   aQl, bh[0], bh[1]);
                MMA4(s[2*nb2+1], aQl, bh[2], bh[3]);
            }
        }

        const int kgb = kt * 64 + (l & 3) * 2;
        float mx0 = -1e30f, mx1 = -1e30f;
        #pragma unroll
        for (int nb = 0; nb < 8; nb++) {
            int kg = kgb + nb * 8;
            if (kg     > qg0)     s[nb][0] = -1e30f;
            if (kg + 1 > qg0)     s[nb][1] = -1e30f;
            if (kg     > qg0 + 8) s[nb][2] = -1e30f;
            if (kg + 1 > qg0 + 8) s[nb][3] = -1e30f;
            mx0 = fmaxf(mx0, fmaxf(s[nb][0], s[nb][1]));
            mx1 = fmaxf(mx1, fmaxf(s[nb][2], s[nb][3]));
        }
        mx0 = fmaxf(mx0, __shfl_xor_sync(0xffffffffu, mx0, 1));
        mx0 = fmaxf(mx0, __shfl_xor_sync(0xffffffffu, mx0, 2));
        mx1 = fmaxf(mx1, __shfl_xor_sync(0xffffffffu, mx1, 1));
        mx1 = fmaxf(mx1, __shfl_xor_sync(0xffffffffu, mx1, 2));

        float mn0 = fmaxf(mr0, mx0), mn1 = fmaxf(mr1, mx1);
        float al0 = __expf(mr0 - mn0), al1 = __expf(mr1 - mn1);
        mr0 = mn0; mr1 = mn1;
        float sum0 = 0.f, sum1 = 0.f;
        #pragma unroll
        for (int nb = 0; nb < 8; nb++) {
            s[nb][0] = __expf(s[nb][0] - mn0);
            s[nb][1] = __expf(s[nb][1] - mn0);
            s[nb][2] = __expf(s[nb][2] - mn1);
            s[nb][3] = __expf(s[nb][3] - mn1);
            sum0 += s[nb][0] + s[nb][1];
            sum1 += s[nb][2] + s[nb][3];
        }
        sum0 += __shfl_xor_sync(0xffffffffu, sum0, 1);
        sum0 += __shfl_xor_sync(0xffffffffu, sum0, 2);
        sum1 += __shfl_xor_sync(0xffffffffu, sum1, 1);
        sum1 += __shfl_xor_sync(0xffffffffu, sum1, 2);
        sl0 = sl0 * al0 + sum0;
        sl1 = sl1 * al1 + sum1;
        #pragma unroll
        for (int f = 0; f < 16; f++) {
            O[f][0] *= al0; O[f][1] *= al0; O[f][2] *= al1; O[f][3] *= al1;
        }

        #pragma unroll
        for (int j = 0; j < 4; j++) {
            uint32_t ph[4], pl[4];
            pk2(s[2*j][0],   s[2*j][1],   ph[0], pl[0]);
            pk2(s[2*j][2],   s[2*j][3],   ph[1], pl[1]);
            pk2(s[2*j+1][0], s[2*j+1][1], ph[2], pl[2]);
            pk2(s[2*j+1][2], s[2*j+1][3], ph[3], pl[3]);
            uint32_t vrow = (uint32_t)(j * 16 + (l & 7) + ((l & 8) ? 8 : 0));
            #pragma unroll
            for (int nb2 = 0; nb2 < 8; nb2++) {
                uint32_t vaddr = st + 32768 +
                    swz256(vrow * 256 + nb2 * 32 + ((l & 16) ? 16 : 0));
                uint32_t vh[4], vl[4];
                LDSM_X4T(vh, vaddr);
                LDSM_X4T(vl, vaddr + 16384);
                MMA4(O[2*nb2],   ph, vh[0], vh[1]);
                MMA4(O[2*nb2+1], ph, vh[2], vh[3]);
                MMA4(O[2*nb2],   ph, vl[0], vl[1]);
                MMA4(O[2*nb2+1], ph, vl[2], vl[3]);
                MMA4(O[2*nb2],   pl, vh[0], vh[1]);
                MMA4(O[2*nb2+1], pl, vh[2], vh[3]);
            }
        }
        __syncthreads();
    }

    const float i0 = 1.0f / sl0, i1 = 1.0f / sl1;
    size_t base0 = (size_t)(b * SS + qg0) * HID + (size_t)h * HD;
    size_t base1 = base0 + (size_t)8 * HID;
    #pragma unroll
    for (int nb = 0; nb < 16; nb++) {
        int col = nb * 8 + (l & 3) * 2;
        uint32_t hi, lo;
        pk2(O[nb][0] * i0, O[nb][1] * i0, hi, lo);
        *(uint32_t*)(g_Ath + base0 + col) = hi;
        *(uint32_t*)(g_Atl + base0 + col) = lo;
        pk2(O[nb][2] * i1, O[nb][3] * i1, hi, lo);
        *(uint32_t*)(g_Ath + base1 + col) = hi;
        *(uint32_t*)(g_Atl + base1 + col) = lo;
    }
}

// ---------------------------------------------------------------------------
extern "C" void kernel_launch(void* const* d_in, const int* in_sizes, int n_in,
                              void* d_out, int out_size)
{
    (void)in_sizes; (void)n_in; (void)out_size;
    const float* x  = (const float*)d_in[0];
    const float* Wq = (const float*)d_in[1];
    const float* Wk = (const float*)d_in[2];
    const float* Wv = (const float*)d_in[3];
    const float* Wo = (const float*)d_in[4];
    float* out = (float*)d_out;

    float *Qp, *Kp;
    __nv_bfloat16 *xh, *xl, *wqh, *wql, *wkh, *wkl, *wvh, *wvl, *woh, *wol;
    __nv_bfloat16 *qh, *ql, *kh, *kl, *vh, *vl, *ath, *atl;
    cudaGetSymbolAddress((void**)&Qp, g_Q);
    cudaGetSymbolAddress((void**)&Kp, g_K);
    cudaGetSymbolAddress((void**)&xh, g_xh);   cudaGetSymbolAddress((void**)&xl, g_xl);
    cudaGetSymbolAddress((void**)&wqh, g_Wqh); cudaGetSymbolAddress((void**)&wql, g_Wql);
    cudaGetSymbolAddress((void**)&wkh, g_Wkh); cudaGetSymbolAddress((void**)&wkl, g_Wkl);
    cudaGetSymbolAddress((void**)&wvh, g_Wvh); cudaGetSymbolAddress((void**)&wvl, g_Wvl);
    cudaGetSymbolAddress((void**)&woh, g_Woh); cudaGetSymbolAddress((void**)&wol, g_Wol);
    cudaGetSymbolAddress((void**)&qh, g_Qh);   cudaGetSymbolAddress((void**)&ql, g_Ql);
    cudaGetSymbolAddress((void**)&kh, g_Kh);   cudaGetSymbolAddress((void**)&kl, g_Kl);
    cudaGetSymbolAddress((void**)&vh, g_Vh);   cudaGetSymbolAddress((void**)&vl, g_Vl);
    cudaGetSymbolAddress((void**)&ath, g_Ath); cudaGetSymbolAddress((void**)&atl, g_Atl);

    cudaFuncSetAttribute(gemm_bf16s, cudaFuncAttributeMaxDynamicSharedMemorySize, GEMM_SMEM);
    cudaFuncSetAttribute(attn_mma, cudaFuncAttributeMaxDynamicSharedMemorySize, ATT_SMEM);

    // conversions first (launches 1-5) so launch #6 (ncu -s 5) is the Q GEMM
    cvt_hl<<<(MR * HID / 4 + 255) / 256, 256>>>(x,  xh,  xl,  MR * HID / 4);
    cvt_hl<<<(HID * HID / 4 + 255) / 256, 256>>>(Wq, wqh, wql, HID * HID / 4);
    cvt_hl<<<(HID * KVD / 4 + 255) / 256, 256>>>(Wk, wkh, wkl, HID * KVD / 4);
    cvt_hl<<<(HID * KVD / 4 + 255) / 256, 256>>>(Wv, wvh, wvl, HID * KVD / 4);
    cvt_hl<<<(HID * HID / 4 + 255) / 256, 256>>>(Wo, woh, wol, HID * HID / 4);

    gemm_bf16s<<<dim3(HID / 128, MR / 128), 256, GEMM_SMEM>>>(
        xh, xl, wqh, wql, Qp, nullptr, nullptr, HID);
    gemm_bf16s<<<dim3(KVD / 128, MR / 128), 256, GEMM_SMEM>>>(
        xh, xl, wkh, wkl, Kp, nullptr, nullptr, KVD);
    gemm_bf16s<<<dim3(KVD / 128, MR / 128), 256, GEMM_SMEM>>>(
        xh, xl, wvh, wvl, nullptr, vh, vl, KVD);

    rope_table_k<<<(SS * 64 + 255) / 256, 256>>>();
    const float scale = 0.08838834764831845f;   // 1/sqrt(128)
    rope_split_k<<<(MR * NHQ  * 64 + 255) / 256, 256>>>(Qp, qh, ql, NHQ, scale);
    rope_split_k<<<(MR * NHKV * 64 + 255) / 256, 256>>>(Kp, kh, kl, NHKV, 1.0f);

    attn_mma<<<dim3(SS / 128, NHQ, BB), 256, ATT_SMEM>>>();

    gemm_bf16s<<<dim3(HID / 128, MR / 128), 256, GEMM_SMEM>>>(
        ath, atl, woh, wol, out, nullptr, nullptr, HID);
}